// round 3
// baseline (speedup 1.0000x reference)
#include <cuda_runtime.h>
#include <cstdint>

#define Hh 512
#define Ww 512
#define TH 56          /* output rows per block; ROWSH = 66 = 6*11          */
#define NT 128         /* threads per block; each handles 2 output columns  */
#define TWC 256        /* output cols per block = 2*NT                      */
#define COLS 266       /* TWC + 10 halo cols                                */
#define CSTR 268       /* shared row stride in pk units (even, 16B align)   */
#define NCH 6          /* chunks of 11 rows                                 */
#define BUFB (11 * CSTR * 8)   /* bytes per chunk buffer */

typedef unsigned long long pk_t;

__device__ __forceinline__ pk_t pk2(float a, float b) {
    pk_t r; asm("mov.b64 %0, {%1, %2};" : "=l"(r) : "f"(a), "f"(b)); return r;
}
__device__ __forceinline__ pk_t padd(pk_t a, pk_t b) {
    pk_t r; asm("add.rn.f32x2 %0, %1, %2;" : "=l"(r) : "l"(a), "l"(b)); return r;
}
__device__ __forceinline__ pk_t pmul(pk_t a, pk_t b) {
    pk_t r; asm("mul.rn.f32x2 %0, %1, %2;" : "=l"(r) : "l"(a), "l"(b)); return r;
}
__device__ __forceinline__ pk_t pfma(pk_t a, pk_t b, pk_t c) {
    pk_t r; asm("fma.rn.f32x2 %0, %1, %2, %3;" : "=l"(r) : "l"(a), "l"(b), "l"(c)); return r;
}
__device__ __forceinline__ float plo(pk_t a) { return __uint_as_float((unsigned)a); }
__device__ __forceinline__ float phi(pk_t a) { return __uint_as_float((unsigned)(a >> 32)); }

__device__ __forceinline__ void cp4(uint32_t saddr, const float* g) {
    asm volatile("cp.async.ca.shared.global [%0], [%1], 4;" :: "r"(saddr), "l"(g) : "memory");
}
__device__ __forceinline__ void cp_commit() {
    asm volatile("cp.async.commit_group;" ::: "memory");
}
__device__ __forceinline__ void cp_wait1() {
    asm volatile("cp.async.wait_group 1;" ::: "memory");
}
__device__ __forceinline__ void cp_wait0() {
    asm volatile("cp.async.wait_group 0;" ::: "memory");
}

// out[b,i,j] = sum_{1<=|a|+|c|<=5} w_{|a|+|c|} * s[b,(i+a)%H,(j+c)%W]   (torus)
// Per row: R_t[j] = x[j-t]+x[j+t]; F_m = sum_t W(m+t) R_t; row r feeds outputs r±m.
// 11 cyclic accumulators stream rows top->bottom; 2 batches packed in f32x2;
// 2 adjacent output columns per thread. Tile fill is fully async via cp.async.
__global__ __launch_bounds__(NT, 4)
void lc_kernel(const float* __restrict__ in, const float* __restrict__ w,
               float* __restrict__ out)
{
    extern __shared__ pk_t sh[];   // 2 chunk buffers, 11*CSTR pk each

    const int tid = threadIdx.x;
    const int j0  = blockIdx.x * TWC;
    const int i0  = blockIdx.y * TH;
    const int bp  = blockIdx.z;

    const float* gA = in  + (size_t)(2 * bp) * (Hh * Ww);
    const float* gB = gA + Hh * Ww;
    float*       oA = out + (size_t)(2 * bp) * (Hh * Ww);
    float*       oB = oA + Hh * Ww;

    uint32_t sbase;
    asm("{ .reg .u64 t; cvta.to.shared.u64 t, %1; cvt.u32.u64 %0, t; }"
        : "=r"(sbase) : "l"(sh));

    // precomputed wrapped column offsets (constant across all rows/chunks)
    const int ca0 = (j0 - 5 + tid) & (Ww - 1);
    const int ca1 = (j0 - 5 + tid + NT) & (Ww - 1);
    const int ca2 = (j0 - 5 + tid + 2 * NT) & (Ww - 1);   // used if tid < COLS-2*NT
    const uint32_t s0 = sbase + tid * 8;
    const uint32_t s1 = sbase + (tid + NT) * 8;
    const uint32_t s2 = sbase + (tid + 2 * NT) * 8;
    const bool tail = (tid < (COLS - 2 * NT));             // tid < 10

    // ---- async load of one 11-row chunk into buffer buf (0/1) ----
    auto load_chunk = [&](int buf, int base_r) {
        const uint32_t b = (uint32_t)buf * BUFB;
#pragma unroll
        for (int r = 0; r < 11; r++) {
            const int gr = (base_r + r) & (Hh - 1);
            const float* rowA = gA + gr * Ww;
            const float* rowB = gB + gr * Ww;
            const uint32_t srow = b + (uint32_t)(r * CSTR * 8);
            cp4(s0 + srow,     rowA + ca0);
            cp4(s0 + srow + 4, rowB + ca0);
            cp4(s1 + srow,     rowA + ca1);
            cp4(s1 + srow + 4, rowB + ca1);
            if (tail) {
                cp4(s2 + srow,     rowA + ca2);
                cp4(s2 + srow + 4, rowB + ca2);
            }
        }
    };

    const pk_t w1 = pk2(w[0], w[0]);
    const pk_t w2 = pk2(w[1], w[1]);
    const pk_t w3 = pk2(w[2], w[2]);
    const pk_t w4 = pk2(w[3], w[3]);
    const pk_t w5 = pk2(w[4], w[4]);
    const pk_t zz = pk2(0.0f, 0.0f);

    pk_t accA[11], accB[11];
#pragma unroll
    for (int s = 0; s < 11; s++) { accA[s] = zz; accB[s] = zz; }

    // prologue: chunks 0 and 1 in flight
    load_chunk(0, i0 - 5);
    cp_commit();
    load_chunk(1, i0 - 5 + 11);
    cp_commit();

    for (int c = 0; c < NCH; c++) {
        if (c >= NCH - 2) cp_wait0(); else cp_wait1();   // chunk c landed
        __syncthreads();

        const pk_t* cur = sh + (c & 1) * (11 * CSTR);

#pragma unroll
        for (int u = 0; u < 11; u++) {
            const int k = c * 11 + u;             // tile row; k % 11 == u
            const pk_t* rp = cur + u * CSTR + 2 * tid;

            pk_t v0, v1, v2, v3, v4, v5, v6, v7, v8, v9, v10, v11;
            {
                const uint4* q = (const uint4*)rp;
                uint4 a = q[0], b = q[1], cq = q[2], d = q[3], e = q[4], f = q[5];
                v0  = ((pk_t)a.y  << 32) | a.x;   v1  = ((pk_t)a.w  << 32) | a.z;
                v2  = ((pk_t)b.y  << 32) | b.x;   v3  = ((pk_t)b.w  << 32) | b.z;
                v4  = ((pk_t)cq.y << 32) | cq.x;  v5  = ((pk_t)cq.w << 32) | cq.z;
                v6  = ((pk_t)d.y  << 32) | d.x;   v7  = ((pk_t)d.w  << 32) | d.z;
                v8  = ((pk_t)e.y  << 32) | e.x;   v9  = ((pk_t)e.w  << 32) | e.z;
                v10 = ((pk_t)f.y  << 32) | f.x;   v11 = ((pk_t)f.w  << 32) | f.z;
            }
            pk_t v12 = rp[12];

            // column A (center v5)
            {
                pk_t R0 = v5;
                pk_t R1 = padd(v4, v6);
                pk_t R2 = padd(v3, v7);
                pk_t R3 = padd(v2, v8);
                pk_t R4 = padd(v1, v9);
                pk_t R5 = padd(v0, v10);
                pk_t F0 = pfma(w5, R5, pfma(w4, R4, pfma(w3, R3, pfma(w2, R2, pmul(w1, R1)))));
                pk_t F1 = pfma(w5, R4, pfma(w4, R3, pfma(w3, R2, pfma(w2, R1, pmul(w1, R0)))));
                pk_t F2 = pfma(w5, R3, pfma(w4, R2, pfma(w3, R1, pmul(w2, R0))));
                pk_t F3 = pfma(w5, R2, pfma(w4, R1, pmul(w3, R0)));
                pk_t F4 = pfma(w5, R1, pmul(w4, R0));
                pk_t F5 = pmul(w5, R0);
                accA[(u + 5)  % 11] = padd(accA[(u + 5)  % 11], F0);
                accA[(u + 6)  % 11] = padd(accA[(u + 6)  % 11], F1);
                accA[(u + 4)  % 11] = padd(accA[(u + 4)  % 11], F1);
                accA[(u + 7)  % 11] = padd(accA[(u + 7)  % 11], F2);
                accA[(u + 3)  % 11] = padd(accA[(u + 3)  % 11], F2);
                accA[(u + 8)  % 11] = padd(accA[(u + 8)  % 11], F3);
                accA[(u + 2)  % 11] = padd(accA[(u + 2)  % 11], F3);
                accA[(u + 9)  % 11] = padd(accA[(u + 9)  % 11], F4);
                accA[(u + 1)  % 11] = padd(accA[(u + 1)  % 11], F4);
                accA[(u + 10) % 11] = padd(accA[(u + 10) % 11], F5);
                accA[u]             = padd(accA[u],             F5);
            }
            // column B (center v6)
            {
                pk_t R0 = v6;
                pk_t R1 = padd(v5, v7);
                pk_t R2 = padd(v4, v8);
                pk_t R3 = padd(v3, v9);
                pk_t R4 = padd(v2, v10);
                pk_t R5 = padd(v1, v11);
                pk_t F0 = pfma(w5, R5, pfma(w4, R4, pfma(w3, R3, pfma(w2, R2, pmul(w1, R1)))));
                pk_t F1 = pfma(w5, R4, pfma(w4, R3, pfma(w3, R2, pfma(w2, R1, pmul(w1, R0)))));
                pk_t F2 = pfma(w5, R3, pfma(w4, R2, pfma(w3, R1, pmul(w2, R0))));
                pk_t F3 = pfma(w5, R2, pfma(w4, R1, pmul(w3, R0)));
                pk_t F4 = pfma(w5, R1, pmul(w4, R0));
                pk_t F5 = pmul(w5, R0);
                accB[(u + 5)  % 11] = padd(accB[(u + 5)  % 11], F0);
                accB[(u + 6)  % 11] = padd(accB[(u + 6)  % 11], F1);
                accB[(u + 4)  % 11] = padd(accB[(u + 4)  % 11], F1);
                accB[(u + 7)  % 11] = padd(accB[(u + 7)  % 11], F2);
                accB[(u + 3)  % 11] = padd(accB[(u + 3)  % 11], F2);
                accB[(u + 8)  % 11] = padd(accB[(u + 8)  % 11], F3);
                accB[(u + 2)  % 11] = padd(accB[(u + 2)  % 11], F3);
                accB[(u + 9)  % 11] = padd(accB[(u + 9)  % 11], F4);
                accB[(u + 1)  % 11] = padd(accB[(u + 1)  % 11], F4);
                accB[(u + 10) % 11] = padd(accB[(u + 10) % 11], F5);
                accB[u]             = padd(accB[u],             F5);
            }

            if (k >= 10) {
                const int o = i0 + k - 10;
                if (o < Hh) {
                    const int oi = o * Ww + j0 + 2 * tid;
                    float2 ra = make_float2(plo(accA[u]), plo(accB[u]));
                    float2 rb = make_float2(phi(accA[u]), phi(accB[u]));
                    *(float2*)(oA + oi) = ra;
                    *(float2*)(oB + oi) = rb;
                }
            }
            accA[u] = zz;
            accB[u] = zz;
        }

        if (c + 2 < NCH) {
            __syncthreads();   // everyone done reading buf[c&1] before refill
            load_chunk(c & 1, i0 - 5 + (c + 2) * 11);
            cp_commit();
        }
    }
}

extern "C" void kernel_launch(void* const* d_in, const int* in_sizes, int n_in,
                              void* d_out, int out_size)
{
    int gi = 0, wi = 1;
    if (in_sizes[0] == 5) { gi = 1; wi = 0; }
    const float* in = (const float*)d_in[gi];
    const float* w  = (const float*)d_in[wi];
    float* out = (float*)d_out;

    int B = in_sizes[gi] / (Hh * Ww);                 // 64
    size_t smem = (size_t)2 * BUFB;                   // 47168 B

    static int attr_set = 0;
    if (!attr_set) {
        cudaFuncSetAttribute(lc_kernel, cudaFuncAttributeMaxDynamicSharedMemorySize, (int)smem);
        attr_set = 1;
    }

    dim3 grid(Ww / TWC, (Hh + TH - 1) / TH, B / 2);   // 2 x 10 x 32 = 640
    lc_kernel<<<grid, NT, smem>>>(in, w, out);
}

// round 4
// speedup vs baseline: 1.5816x; 1.5816x over previous
#include <cuda_runtime.h>
#include <cstdint>

#define Hh 512
#define Ww 512
#define NT 256            /* threads: each owns 2 adjacent columns (512 total) */
#define TH 56             /* output rows per block; 56+10 = 66 = 6*11          */
#define NCH 6             /* chunks of 11 rows                                 */
#define ROWB 2048         /* bytes per smem row = 512 floats                   */
#define CHB (11 * ROWB)   /* 22528 bytes per chunk buffer                      */

typedef unsigned long long pk_t;   /* {lo=col c, hi=col c+1} f32x2 */

__device__ __forceinline__ pk_t pk2(float a, float b) {
    pk_t r; asm("mov.b64 %0, {%1, %2};" : "=l"(r) : "f"(a), "f"(b)); return r;
}
__device__ __forceinline__ void punpack(pk_t a, float& lo, float& hi) {
    asm("mov.b64 {%0, %1}, %2;" : "=f"(lo), "=f"(hi) : "l"(a));
}
__device__ __forceinline__ pk_t padd(pk_t a, pk_t b) {
    pk_t r; asm("add.rn.f32x2 %0, %1, %2;" : "=l"(r) : "l"(a), "l"(b)); return r;
}
__device__ __forceinline__ pk_t pmul(pk_t a, pk_t b) {
    pk_t r; asm("mul.rn.f32x2 %0, %1, %2;" : "=l"(r) : "l"(a), "l"(b)); return r;
}
__device__ __forceinline__ pk_t pfma(pk_t a, pk_t b, pk_t c) {
    pk_t r; asm("fma.rn.f32x2 %0, %1, %2, %3;" : "=l"(r) : "l"(a), "l"(b), "l"(c)); return r;
}

__device__ __forceinline__ void mbar_init(uint32_t mb, uint32_t cnt) {
    asm volatile("mbarrier.init.shared.b64 [%0], %1;" :: "r"(mb), "r"(cnt) : "memory");
}
__device__ __forceinline__ void mbar_expect_tx(uint32_t mb, uint32_t bytes) {
    asm volatile("mbarrier.arrive.expect_tx.shared.b64 _, [%0], %1;" :: "r"(mb), "r"(bytes) : "memory");
}
__device__ __forceinline__ void mbar_wait(uint32_t mb, uint32_t parity) {
    uint32_t done;
    asm volatile("{\n\t.reg .pred p;\n\t"
                 "mbarrier.try_wait.parity.acquire.cta.shared::cta.b64 p, [%1], %2;\n\t"
                 "selp.b32 %0, 1, 0, p;\n\t}"
                 : "=r"(done) : "r"(mb), "r"(parity) : "memory");
    if (!done) {
        asm volatile("{\n\t.reg .pred P1;\n\t"
                     "W_%=:\n\t"
                     "mbarrier.try_wait.parity.acquire.cta.shared::cta.b64 P1, [%0], %1, 0x989680;\n\t"
                     "@P1 bra.uni D_%=;\n\t"
                     "bra.uni W_%=;\n\t"
                     "D_%=:\n\t}"
                     :: "r"(mb), "r"(parity) : "memory");
    }
}
__device__ __forceinline__ void bulk_cp(uint32_t dst, const float* src, uint32_t bytes, uint32_t mb) {
    asm volatile("cp.async.bulk.shared::cta.global.mbarrier::complete_tx::bytes [%0], [%1], %2, [%3];"
                 :: "r"(dst), "l"(src), "r"(bytes), "r"(mb) : "memory");
}

// out[b,i,j] = sum_{1<=|a|+|c|<=5} w_{|a|+|c|} * s[b,(i+a)%512,(j+c)%512]
// Per input row: R_t[j] = x[j-t]+x[j+t]; F_m = sum_t W(m+t) R_t; row r feeds out rows r±m.
// 11 cyclic f32x2 accumulators (2 adjacent columns packed). Rows stream via
// cp.async.bulk double-buffered 11-row chunks (one 2048B copy per row, single thread).
__global__ __launch_bounds__(NT, 3)
void lc_kernel(const float* __restrict__ in, const float* __restrict__ w,
               float* __restrict__ out)
{
    extern __shared__ float sh[];                    // 2 * CHB bytes
    __shared__ unsigned long long mbar[2];

    const int tid = threadIdx.x;
    const int i0  = blockIdx.x * TH;
    const float* g = in  + (size_t)blockIdx.y * (Hh * Ww);
    float*       o = out + (size_t)blockIdx.y * (Hh * Ww);

    uint32_t sbase, mb0;
    asm("{ .reg .u64 t; cvta.to.shared.u64 t, %1; cvt.u32.u64 %0, t; }" : "=r"(sbase) : "l"(sh));
    asm("{ .reg .u64 t; cvta.to.shared.u64 t, %1; cvt.u32.u64 %0, t; }" : "=r"(mb0) : "l"(&mbar[0]));

    if (tid == 0) {
        mbar_init(mb0, 1);
        mbar_init(mb0 + 8, 1);
        asm volatile("fence.proxy.async.shared::cta;" ::: "memory");
    }
    __syncthreads();

    auto issue = [&](int c) {
        if (tid == 0) {
            const uint32_t mb  = mb0 + (c & 1) * 8;
            const uint32_t dst = sbase + (c & 1) * CHB;
            mbar_expect_tx(mb, CHB);
            const int base_r = i0 - 5 + c * 11;
#pragma unroll
            for (int r = 0; r < 11; r++) {
                const int gr = (base_r + r) & (Hh - 1);
                bulk_cp(dst + r * ROWB, g + gr * Ww, ROWB, mb);
            }
        }
    };

    issue(0);
    issue(1);

    const pk_t w1 = pk2(w[0], w[0]);
    const pk_t w2 = pk2(w[1], w[1]);
    const pk_t w3 = pk2(w[2], w[2]);
    const pk_t w4 = pk2(w[3], w[3]);
    const pk_t w5 = pk2(w[4], w[4]);
    const pk_t zz = pk2(0.0f, 0.0f);

    // per-thread wrapped column byte offsets (constant across rows/chunks)
    const int c0 = 2 * tid;
    const uint32_t ob_m2 = (uint32_t)(((c0 - 4 + Ww) & (Ww - 1)) * 4);   // {c-4,c-3}
    const uint32_t ob_m1 = (uint32_t)(((c0 - 2 + Ww) & (Ww - 1)) * 4);   // {c-2,c-1}
    const uint32_t ob_0  = (uint32_t)(c0 * 4);                           // {c,  c+1}
    const uint32_t ob_1  = (uint32_t)(((c0 + 2) & (Ww - 1)) * 4);        // {c+2,c+3}
    const uint32_t ob_2  = (uint32_t)(((c0 + 4) & (Ww - 1)) * 4);        // {c+4,c+5}
    const uint32_t ob_lo = (uint32_t)(((c0 - 5 + Ww) & (Ww - 1)) * 4);   // x[c-5]
    const uint32_t ob_hi = (uint32_t)(((c0 + 6) & (Ww - 1)) * 4);        // x[c+6]

    pk_t acc[11];
#pragma unroll
    for (int s = 0; s < 11; s++) acc[s] = zz;

    const char* shc = (const char*)sh;

    for (int c = 0; c < NCH; c++) {
        mbar_wait(mb0 + (c & 1) * 8, (c >> 1) & 1);

        const char* buf = shc + (c & 1) * CHB;
        // base pointers for this chunk (LDS [R+imm] with imm = u*ROWB)
        const char* p_m2 = buf + ob_m2;
        const char* p_m1 = buf + ob_m1;
        const char* p_0  = buf + ob_0;
        const char* p_1  = buf + ob_1;
        const char* p_2  = buf + ob_2;
        const char* p_lo = buf + ob_lo;
        const char* p_hi = buf + ob_hi;

#pragma unroll
        for (int u = 0; u < 11; u++) {
            const int off = u * ROWB;
            pk_t Dm2 = *(const pk_t*)(p_m2 + off);
            pk_t Dm1 = *(const pk_t*)(p_m1 + off);
            pk_t D0  = *(const pk_t*)(p_0  + off);
            pk_t D1  = *(const pk_t*)(p_1  + off);
            pk_t D2  = *(const pk_t*)(p_2  + off);
            float xm5 = *(const float*)(p_lo + off);
            float xp6 = *(const float*)(p_hi + off);

            float dm2l, dm2h, dm1l, dm1h, d0l, d0h, d1l, d1h, d2l, d2h;
            punpack(Dm2, dm2l, dm2h);
            punpack(Dm1, dm1l, dm1h);
            punpack(D0,  d0l,  d0h);
            punpack(D1,  d1l,  d1h);
            punpack(D2,  d2l,  d2h);

            pk_t R0 = D0;
            pk_t R2 = padd(Dm1, D1);
            pk_t R4 = padd(Dm2, D2);
            pk_t R1 = pk2(dm1h + d0h, d0l + d1l);
            pk_t R3 = pk2(dm2h + d1h, dm1l + d2l);
            pk_t R5 = pk2(xm5  + d2h, dm2l + xp6);

            pk_t F0 = pfma(w5, R5, pfma(w4, R4, pfma(w3, R3, pfma(w2, R2, pmul(w1, R1)))));
            pk_t F1 = pfma(w5, R4, pfma(w4, R3, pfma(w3, R2, pfma(w2, R1, pmul(w1, R0)))));
            pk_t F2 = pfma(w5, R3, pfma(w4, R2, pfma(w3, R1, pmul(w2, R0))));
            pk_t F3 = pfma(w5, R2, pfma(w4, R1, pmul(w3, R0)));
            pk_t F4 = pfma(w5, R1, pmul(w4, R0));
            pk_t F5 = pmul(w5, R0);

            acc[(u + 5)  % 11] = padd(acc[(u + 5)  % 11], F0);
            acc[(u + 6)  % 11] = padd(acc[(u + 6)  % 11], F1);
            acc[(u + 4)  % 11] = padd(acc[(u + 4)  % 11], F1);
            acc[(u + 7)  % 11] = padd(acc[(u + 7)  % 11], F2);
            acc[(u + 3)  % 11] = padd(acc[(u + 3)  % 11], F2);
            acc[(u + 8)  % 11] = padd(acc[(u + 8)  % 11], F3);
            acc[(u + 2)  % 11] = padd(acc[(u + 2)  % 11], F3);
            acc[(u + 9)  % 11] = padd(acc[(u + 9)  % 11], F4);
            acc[(u + 1)  % 11] = padd(acc[(u + 1)  % 11], F4);
            acc[(u + 10) % 11] = padd(acc[(u + 10) % 11], F5);
            acc[u]             = padd(acc[u],             F5);

            const int k = c * 11 + u;
            if (k >= 10) {
                const int orow = i0 + k - 10;
                if (orow < Hh) {
                    *(pk_t*)(o + orow * Ww + c0) = acc[u];   // STG.64: {col c, col c+1}
                }
            }
            acc[u] = zz;
        }

        __syncthreads();                 // all lanes done reading buf (c&1)
        if (c + 2 < NCH) issue(c + 2);   // refill it for chunk c+2
    }
}

extern "C" void kernel_launch(void* const* d_in, const int* in_sizes, int n_in,
                              void* d_out, int out_size)
{
    int gi = 0, wi = 1;
    if (in_sizes[0] == 5) { gi = 1; wi = 0; }
    const float* in = (const float*)d_in[gi];
    const float* w  = (const float*)d_in[wi];
    float* out = (float*)d_out;

    int B = in_sizes[gi] / (Hh * Ww);                 // 64
    size_t smem = (size_t)2 * CHB;                    // 45056 B

    static int attr_set = 0;
    if (!attr_set) {
        cudaFuncSetAttribute(lc_kernel, cudaFuncAttributeMaxDynamicSharedMemorySize, (int)smem);
        attr_set = 1;
    }

    dim3 grid((Hh + TH - 1) / TH, B);                 // 10 x 64 = 640 blocks
    lc_kernel<<<grid, NT, smem>>>(in, w, out);
}

// round 5
// speedup vs baseline: 1.6848x; 1.0652x over previous
#include <cuda_runtime.h>
#include <cstdint>

#define Hh 512
#define Ww 512
#define NT 128            /* threads; each owns 2 adjacent output columns     */
#define TWC 256           /* output columns per block                         */
#define TH 67             /* output rows per block; 67+10 = 77 = 7*11         */
#define NCH 7             /* chunks of 11 rows                                */
#define SROWF 272         /* smem row width in floats: cols [j0-8, j0+264)    */
#define ROWB (SROWF * 4)  /* 1088 bytes per smem row                          */
#define CHB (11 * ROWB)   /* 11968 bytes per chunk buffer                     */

typedef unsigned long long pk_t;   /* {lo=col c, hi=col c+1} f32x2 */

__device__ __forceinline__ pk_t pk2(float a, float b) {
    pk_t r; asm("mov.b64 %0, {%1, %2};" : "=l"(r) : "f"(a), "f"(b)); return r;
}
__device__ __forceinline__ void punpack(pk_t a, float& lo, float& hi) {
    asm("mov.b64 {%0, %1}, %2;" : "=f"(lo), "=f"(hi) : "l"(a));
}
__device__ __forceinline__ pk_t padd(pk_t a, pk_t b) {
    pk_t r; asm("add.rn.f32x2 %0, %1, %2;" : "=l"(r) : "l"(a), "l"(b)); return r;
}
__device__ __forceinline__ pk_t pmul(pk_t a, pk_t b) {
    pk_t r; asm("mul.rn.f32x2 %0, %1, %2;" : "=l"(r) : "l"(a), "l"(b)); return r;
}
__device__ __forceinline__ pk_t pfma(pk_t a, pk_t b, pk_t c) {
    pk_t r; asm("fma.rn.f32x2 %0, %1, %2, %3;" : "=l"(r) : "l"(a), "l"(b), "l"(c)); return r;
}

__device__ __forceinline__ void mbar_init(uint32_t mb, uint32_t cnt) {
    asm volatile("mbarrier.init.shared.b64 [%0], %1;" :: "r"(mb), "r"(cnt) : "memory");
}
__device__ __forceinline__ void mbar_expect_tx(uint32_t mb, uint32_t bytes) {
    asm volatile("mbarrier.arrive.expect_tx.shared.b64 _, [%0], %1;" :: "r"(mb), "r"(bytes) : "memory");
}
__device__ __forceinline__ void mbar_wait(uint32_t mb, uint32_t parity) {
    uint32_t done;
    asm volatile("{\n\t.reg .pred p;\n\t"
                 "mbarrier.try_wait.parity.acquire.cta.shared::cta.b64 p, [%1], %2;\n\t"
                 "selp.b32 %0, 1, 0, p;\n\t}"
                 : "=r"(done) : "r"(mb), "r"(parity) : "memory");
    if (!done) {
        asm volatile("{\n\t.reg .pred P1;\n\t"
                     "W_%=:\n\t"
                     "mbarrier.try_wait.parity.acquire.cta.shared::cta.b64 P1, [%0], %1, 0x989680;\n\t"
                     "@P1 bra.uni D_%=;\n\t"
                     "bra.uni W_%=;\n\t"
                     "D_%=:\n\t}"
                     :: "r"(mb), "r"(parity) : "memory");
    }
}
__device__ __forceinline__ void bulk_cp(uint32_t dst, const float* src, uint32_t bytes, uint32_t mb) {
    asm volatile("cp.async.bulk.shared::cta.global.mbarrier::complete_tx::bytes [%0], [%1], %2, [%3];"
                 :: "r"(dst), "l"(src), "r"(bytes), "r"(mb) : "memory");
}

// out[b,i,j] = sum_{1<=|a|+|c|<=5} w_{|a|+|c|} * s[b,(i+a)%512,(j+c)%512]
// Per input row: R_t[j] = x[j-t]+x[j+t]; F_m = sum_t W(m+t) R_t; row r feeds out rows r±m.
// 11 cyclic f32x2 accumulators (2 adjacent columns packed per thread).
// Rows stream via double-buffered cp.async.bulk 11-row chunks; column wrap is
// resolved at fill time so all inner-loop smem offsets are constant & aligned.
__global__ __launch_bounds__(NT, 7)
void lc_kernel(const float* __restrict__ in, const float* __restrict__ w,
               float* __restrict__ out)
{
    extern __shared__ float sh[];                    // 2 * CHB bytes
    __shared__ unsigned long long mbar[2];

    const int tid = threadIdx.x;
    const int j0  = blockIdx.x * TWC;                // 0 or 256
    const int i0  = blockIdx.y * TH;
    const float* g = in  + (size_t)blockIdx.z * (Hh * Ww);
    float*       o = out + (size_t)blockIdx.z * (Hh * Ww);

    uint32_t sbase, mb0;
    asm("{ .reg .u64 t; cvta.to.shared.u64 t, %1; cvt.u32.u64 %0, t; }" : "=r"(sbase) : "l"(sh));
    asm("{ .reg .u64 t; cvta.to.shared.u64 t, %1; cvt.u32.u64 %0, t; }" : "=r"(mb0) : "l"(&mbar[0]));

    if (tid == 0) {
        mbar_init(mb0, 1);
        mbar_init(mb0 + 8, 1);
        asm volatile("fence.proxy.async.shared::cta;" ::: "memory");
    }
    __syncthreads();

    // fill window = global cols [j0-8, j0+264) mod 512; wrap split (both tiles wrap)
    const int ws = (j0 - 8) & (Ww - 1);              // 504 or 248 (mult of 4)
    const int n1 = Ww - ws;                          // floats before wrap: 8 or 264
    const uint32_t b1 = (uint32_t)(n1 * 4);          // 32 or 1056 (16B multiples)

    auto issue = [&](int c) {
        if (tid == 0) {
            const uint32_t mb  = mb0 + (c & 1) * 8;
            uint32_t dst = sbase + (c & 1) * CHB;
            mbar_expect_tx(mb, CHB);
            const int base_r = i0 - 5 + c * 11;
#pragma unroll
            for (int r = 0; r < 11; r++) {
                const int gr = (base_r + r) & (Hh - 1);
                const float* rowg = g + gr * Ww;
                bulk_cp(dst,      rowg + ws, b1,        mb);
                bulk_cp(dst + b1, rowg,      ROWB - b1, mb);
                dst += ROWB;
            }
        }
    };

    issue(0);
    issue(1);

    const pk_t w1 = pk2(w[0], w[0]);
    const pk_t w2 = pk2(w[1], w[1]);
    const pk_t w3 = pk2(w[2], w[2]);
    const pk_t w4 = pk2(w[3], w[3]);
    const pk_t w5 = pk2(w[4], w[4]);
    const pk_t zz = pk2(0.0f, 0.0f);

    // per-thread smem byte offsets within a row (global col j0+x -> float idx x+8)
    const int t2 = 2 * tid;
    const uint32_t ob_m2 = (uint32_t)((t2 + 4)  * 4);   // {c-4,c-3}
    const uint32_t ob_m1 = (uint32_t)((t2 + 6)  * 4);   // {c-2,c-1}
    const uint32_t ob_0  = (uint32_t)((t2 + 8)  * 4);   // {c,  c+1}
    const uint32_t ob_1  = (uint32_t)((t2 + 10) * 4);   // {c+2,c+3}
    const uint32_t ob_2  = (uint32_t)((t2 + 12) * 4);   // {c+4,c+5}
    const uint32_t ob_lo = (uint32_t)((t2 + 3)  * 4);   // x[c-5]
    const uint32_t ob_hi = (uint32_t)((t2 + 14) * 4);   // x[c+6]

    pk_t acc[11];
#pragma unroll
    for (int s = 0; s < 11; s++) acc[s] = zz;

    const char* shc = (const char*)sh;

    for (int c = 0; c < NCH; c++) {
        mbar_wait(mb0 + (c & 1) * 8, (c >> 1) & 1);

        const char* buf = shc + (c & 1) * CHB;
        const char* p_m2 = buf + ob_m2;
        const char* p_m1 = buf + ob_m1;
        const char* p_0  = buf + ob_0;
        const char* p_1  = buf + ob_1;
        const char* p_2  = buf + ob_2;
        const char* p_lo = buf + ob_lo;
        const char* p_hi = buf + ob_hi;

#pragma unroll
        for (int u = 0; u < 11; u++) {
            const int off = u * ROWB;
            pk_t Dm2 = *(const pk_t*)(p_m2 + off);
            pk_t Dm1 = *(const pk_t*)(p_m1 + off);
            pk_t D0  = *(const pk_t*)(p_0  + off);
            pk_t D1  = *(const pk_t*)(p_1  + off);
            pk_t D2  = *(const pk_t*)(p_2  + off);
            float xm5 = *(const float*)(p_lo + off);
            float xp6 = *(const float*)(p_hi + off);

            float dm2l, dm2h, dm1l, dm1h, d0l, d0h, d1l, d1h, d2l, d2h;
            punpack(Dm2, dm2l, dm2h);
            punpack(Dm1, dm1l, dm1h);
            punpack(D0,  d0l,  d0h);
            punpack(D1,  d1l,  d1h);
            punpack(D2,  d2l,  d2h);

            pk_t R0 = D0;
            pk_t R2 = padd(Dm1, D1);
            pk_t R4 = padd(Dm2, D2);
            pk_t R1 = pk2(dm1h + d0h, d0l + d1l);
            pk_t R3 = pk2(dm2h + d1h, dm1l + d2l);
            pk_t R5 = pk2(xm5  + d2h, dm2l + xp6);

            pk_t F0 = pfma(w5, R5, pfma(w4, R4, pfma(w3, R3, pfma(w2, R2, pmul(w1, R1)))));
            pk_t F1 = pfma(w5, R4, pfma(w4, R3, pfma(w3, R2, pfma(w2, R1, pmul(w1, R0)))));
            pk_t F2 = pfma(w5, R3, pfma(w4, R2, pfma(w3, R1, pmul(w2, R0))));
            pk_t F3 = pfma(w5, R2, pfma(w4, R1, pmul(w3, R0)));
            pk_t F4 = pfma(w5, R1, pmul(w4, R0));
            pk_t F5 = pmul(w5, R0);

            acc[(u + 5)  % 11] = padd(acc[(u + 5)  % 11], F0);
            acc[(u + 6)  % 11] = padd(acc[(u + 6)  % 11], F1);
            acc[(u + 4)  % 11] = padd(acc[(u + 4)  % 11], F1);
            acc[(u + 7)  % 11] = padd(acc[(u + 7)  % 11], F2);
            acc[(u + 3)  % 11] = padd(acc[(u + 3)  % 11], F2);
            acc[(u + 8)  % 11] = padd(acc[(u + 8)  % 11], F3);
            acc[(u + 2)  % 11] = padd(acc[(u + 2)  % 11], F3);
            acc[(u + 9)  % 11] = padd(acc[(u + 9)  % 11], F4);
            acc[(u + 1)  % 11] = padd(acc[(u + 1)  % 11], F4);
            acc[(u + 10) % 11] = padd(acc[(u + 10) % 11], F5);
            acc[u]             = padd(acc[u],             F5);

            const int k = c * 11 + u;
            if (k >= 10) {
                const int orow = i0 + k - 10;
                if (orow < Hh) {
                    *(pk_t*)(o + orow * Ww + j0 + t2) = acc[u];   // STG.64
                }
            }
            acc[u] = zz;
        }

        __syncthreads();                 // all lanes done reading buf (c&1)
        if (c + 2 < NCH) issue(c + 2);   // refill for chunk c+2
    }
}

extern "C" void kernel_launch(void* const* d_in, const int* in_sizes, int n_in,
                              void* d_out, int out_size)
{
    int gi = 0, wi = 1;
    if (in_sizes[0] == 5) { gi = 1; wi = 0; }
    const float* in = (const float*)d_in[gi];
    const float* w  = (const float*)d_in[wi];
    float* out = (float*)d_out;

    int B = in_sizes[gi] / (Hh * Ww);                 // 64
    size_t smem = (size_t)2 * CHB;                    // 23936 B

    static int attr_set = 0;
    if (!attr_set) {
        cudaFuncSetAttribute(lc_kernel, cudaFuncAttributeMaxDynamicSharedMemorySize, (int)smem);
        attr_set = 1;
    }

    dim3 grid(Ww / TWC, (Hh + TH - 1) / TH, B);       // 2 x 8 x 64 = 1024 blocks
    lc_kernel<<<grid, NT, smem>>>(in, w, out);
}